// round 6
// baseline (speedup 1.0000x reference)
#include <cuda_runtime.h>
#include <cstdint>

// Fused causal linear attention (elu+1), chunked, tf32 mma, persistent state,
// cp.async double-buffered pipeline. [B=8, L=2048, H=16, D=64], chunk C=128.
// One block (256 thr) per (batch,head) pair; 128 blocks.

#define BB 8
#define LL 2048
#define HH 16
#define DD 64
#define MM 64
#define CC 128
#define NC (LL/CC)      // 16
#define NP (BB*HH)      // 128
#define EPSV 1e-6f

// smem layout (floats):
//  buf[2]: Q[128][68], K[128][68], V[128][72]  (raw -> converted in place)
//  Ss[64][72] running state, kc[64] running ksum
#define QK_STR 68
#define V_STR  72
#define OFF_Q  0
#define OFF_K  (128*QK_STR)
#define OFF_V  (2*128*QK_STR)
#define BUF_FLOATS (2*128*QK_STR + 128*V_STR)     // 26624
#define OFF_SS (2*BUF_FLOATS)
#define OFF_KC (OFF_SS + 64*V_STR)
#define SMEM_FLOATS (OFF_KC + 64)                 // 57920
#define SMEM_BYTES  (SMEM_FLOATS * 4)             // 231680 <= 232448

__device__ __forceinline__ float phi(float x) {
    return x > 0.f ? x + 1.f : __expf(x);
}
__device__ __forceinline__ float tf32r(float x) {
    uint32_t u; asm("cvt.rna.tf32.f32 %0, %1;" : "=r"(u) : "f"(x));
    return __uint_as_float(u);
}
#define AS_U(x) __float_as_uint(x)

__device__ __forceinline__ void mma8(float* c, uint32_t a0, uint32_t a1,
                                     uint32_t a2, uint32_t a3,
                                     uint32_t b0, uint32_t b1) {
    asm volatile(
        "mma.sync.aligned.m16n8k8.row.col.f32.tf32.tf32.f32 "
        "{%0,%1,%2,%3}, {%4,%5,%6,%7}, {%8,%9}, {%0,%1,%2,%3};"
        : "+f"(c[0]), "+f"(c[1]), "+f"(c[2]), "+f"(c[3])
        : "r"(a0), "r"(a1), "r"(a2), "r"(a3), "r"(b0), "r"(b1));
}

__device__ __forceinline__ void cp16(uint32_t dst, const float* src) {
    asm volatile("cp.async.ca.shared.global [%0], [%1], 16;"
                 :: "r"(dst), "l"(src) : "memory");
}
#define CP_COMMIT() asm volatile("cp.async.commit_group;" ::: "memory")
#define CP_WAIT1()  asm volatile("cp.async.wait_group 1;" ::: "memory")
#define CP_WAIT0()  asm volatile("cp.async.wait_group 0;" ::: "memory")

// Issue the raw loads for chunk c into buffer buf (each thread: 8 e-slices x 3).
__device__ __forceinline__ void issue_chunk(uint32_t smem_u32, int buf,
                                            size_t base, int tid,
                                            const float* q, const float* k,
                                            const float* v) {
    uint32_t b0 = smem_u32 + (uint32_t)(buf * BUF_FLOATS) * 4;
#pragma unroll
    for (int it = 0; it < 8; it++) {
        int e = tid + it * 256;
        int j = e >> 4, d4 = (e & 15) * 4;
        size_t g = base + (size_t)j * HH * DD + d4;
        cp16(b0 + (OFF_Q + j * QK_STR + d4) * 4, q + g);
        cp16(b0 + (OFF_K + j * QK_STR + d4) * 4, k + g);
        cp16(b0 + (OFF_V + j * V_STR  + d4) * 4, v + g);
    }
    CP_COMMIT();
}

__global__ void __launch_bounds__(256, 1)
fused_lin_attn(const float* __restrict__ qin, const float* __restrict__ kin,
               const float* __restrict__ vin, float* __restrict__ out) {
    extern __shared__ float sm[];
    uint32_t smem_u32 = (uint32_t)__cvta_generic_to_shared(sm);
    float* Ss = sm + OFF_SS;
    float* kc = sm + OFF_KC;

    int p = blockIdx.x;
    int n = p >> 4, h = p & 15;
    int tid = threadIdx.x;
    int w = tid >> 5, lane = tid & 31, gq = lane >> 2, t = lane & 3;
    int m0 = w * 16;
    int ilo = m0 + gq, ihi = ilo + 8;
    const int NT1 = 2 * w + 2;          // triangular tile count for this warp
    int d0 = (w >> 1) * 16;             // KtV tile mapping
    int nb = (w & 1) * 32;
    int srcA = (lane & ~3) | (t >> 1);  // quad shuffle sources for transpose
    int srcB = srcA + 2;
    int sel = t & 1;

    for (int e = tid; e < 64 * V_STR; e += 256) Ss[e] = 0.f;
    if (tid < DD) kc[tid] = 0.f;
    __syncthreads();

    size_t pbase = ((size_t)n * LL * HH + h) * DD;

    // prologue: prefetch chunk 0
    issue_chunk(smem_u32, 0, pbase, tid, qin, kin, vin);

    for (int c = 0; c < NC; c++) {
        int buf = c & 1;
        float* Qs = sm + buf * BUF_FLOATS + OFF_Q;
        float* Ks = sm + buf * BUF_FLOATS + OFF_K;
        float* Vs = sm + buf * BUF_FLOATS + OFF_V;
        size_t base = pbase + (size_t)(c * CC) * HH * DD;

        if (c + 1 < NC) {
            issue_chunk(smem_u32, buf ^ 1,
                        pbase + (size_t)((c + 1) * CC) * HH * DD,
                        tid, qin, kin, vin);
            CP_WAIT1();
        } else {
            CP_WAIT0();
        }

        // ---- convert own slices in place: phi+tf32 on Q,K; tf32 on V ----
#pragma unroll
        for (int it = 0; it < 8; it++) {
            int e = tid + it * 256;
            int j = e >> 4, d4 = (e & 15) * 4;
            float4* qp = (float4*)(Qs + j * QK_STR + d4);
            float4 qv = *qp;
            qv.x = tf32r(phi(qv.x)); qv.y = tf32r(phi(qv.y));
            qv.z = tf32r(phi(qv.z)); qv.w = tf32r(phi(qv.w));
            *qp = qv;
            float4* kp = (float4*)(Ks + j * QK_STR + d4);
            float4 kv = *kp;
            kv.x = tf32r(phi(kv.x)); kv.y = tf32r(phi(kv.y));
            kv.z = tf32r(phi(kv.z)); kv.w = tf32r(phi(kv.w));
            *kp = kv;
            float4* vp = (float4*)(Vs + j * V_STR + d4);
            float4 vv = *vp;
            vv.x = tf32r(vv.x); vv.y = tf32r(vv.y);
            vv.z = tf32r(vv.z); vv.w = tf32r(vv.w);
            *vp = vv;
        }
        __syncthreads();                                   // SYNC1

        // ---- GEMM1: A = phi(Q) phi(K)^T, warp-private rows m0..m0+15 ----
        float acc[16][4];
#pragma unroll
        for (int i = 0; i < 16; i++)
#pragma unroll
            for (int j = 0; j < 4; j++) acc[i][j] = 0.f;

#pragma unroll
        for (int kt = 0; kt < 8; kt++) {
            int k0 = kt * 8;
            uint32_t a0 = AS_U(Qs[ilo * QK_STR + k0 + t]);
            uint32_t a1 = AS_U(Qs[ihi * QK_STR + k0 + t]);
            uint32_t a2 = AS_U(Qs[ilo * QK_STR + k0 + t + 4]);
            uint32_t a3 = AS_U(Qs[ihi * QK_STR + k0 + t + 4]);
#pragma unroll
            for (int nt = 0; nt < 16; nt++) {
                if (nt >= NT1) break;
                int n0 = nt * 8;
                uint32_t b0 = AS_U(Ks[(n0 + gq) * QK_STR + k0 + t]);
                uint32_t b1 = AS_U(Ks[(n0 + gq) * QK_STR + k0 + t + 4]);
                mma8(acc[nt], a0, a1, a2, a3, b0, b1);
            }
        }

        // ---- mask + tf32-round in place + row sums ----
        float rlo = 0.f, rhi = 0.f;
#pragma unroll
        for (int nt = 0; nt < 16; nt++) {
            if (nt >= NT1) break;
            int jc0 = nt * 8 + 2 * t, jc1 = jc0 + 1;
            float c0 = (jc0 <= ilo) ? acc[nt][0] : 0.f;
            float c1 = (jc1 <= ilo) ? acc[nt][1] : 0.f;
            float c2 = (jc0 <= ihi) ? acc[nt][2] : 0.f;
            float c3 = (jc1 <= ihi) ? acc[nt][3] : 0.f;
            rlo += c0 + c1; rhi += c2 + c3;
            acc[nt][0] = tf32r(c0); acc[nt][1] = tf32r(c1);
            acc[nt][2] = tf32r(c2); acc[nt][3] = tf32r(c3);
        }
        // z = rowsum + q.kcum + eps (quad-reduced)
        float qlo = 0.f, qhi = 0.f;
#pragma unroll
        for (int i = 0; i < 16; i++) {
            int d = t * 16 + i;
            float kcd = kc[d];
            qlo += Qs[ilo * QK_STR + d] * kcd;
            qhi += Qs[ihi * QK_STR + d] * kcd;
        }
        rlo += qlo; rhi += qhi;
        rlo += __shfl_xor_sync(0xffffffffu, rlo, 1);
        rlo += __shfl_xor_sync(0xffffffffu, rlo, 2);
        rhi += __shfl_xor_sync(0xffffffffu, rhi, 1);
        rhi += __shfl_xor_sync(0xffffffffu, rhi, 2);
        float izlo = 1.f / (rlo + EPSV);
        float izhi = 1.f / (rhi + EPSV);

        // ---- GEMM2: out = A*V + Qs*S_prev ; A-fragments via quad shuffle ----
        float acc2[8][4];
#pragma unroll
        for (int i = 0; i < 8; i++)
#pragma unroll
            for (int j = 0; j < 4; j++) acc2[i][j] = 0.f;

#pragma unroll
        for (int kt = 0; kt < 16; kt++) {
            if (kt >= NT1) break;
            // transpose D-frag (rows ilo/ihi, cols 2t,2t+1) -> A-frag (cols t,t+4)
            float v00 = __shfl_sync(0xffffffffu, acc[kt][0], srcA);
            float v01 = __shfl_sync(0xffffffffu, acc[kt][1], srcA);
            float v02 = __shfl_sync(0xffffffffu, acc[kt][0], srcB);
            float v03 = __shfl_sync(0xffffffffu, acc[kt][1], srcB);
            uint32_t a0 = AS_U(sel ? v01 : v00);
            uint32_t a2 = AS_U(sel ? v03 : v02);
            float v10 = __shfl_sync(0xffffffffu, acc[kt][2], srcA);
            float v11 = __shfl_sync(0xffffffffu, acc[kt][3], srcA);
            float v12 = __shfl_sync(0xffffffffu, acc[kt][2], srcB);
            float v13 = __shfl_sync(0xffffffffu, acc[kt][3], srcB);
            uint32_t a1 = AS_U(sel ? v11 : v10);
            uint32_t a3 = AS_U(sel ? v13 : v12);
            int k0 = kt * 8;
#pragma unroll
            for (int nt = 0; nt < 8; nt++) {
                int n0 = nt * 8;
                uint32_t b0 = AS_U(Vs[(k0 + t) * V_STR + n0 + gq]);
                uint32_t b1 = AS_U(Vs[(k0 + t + 4) * V_STR + n0 + gq]);
                mma8(acc2[nt], a0, a1, a2, a3, b0, b1);
            }
        }
        if (c > 0) {
#pragma unroll
            for (int kt = 0; kt < 8; kt++) {
                int k0 = kt * 8;
                uint32_t a0 = AS_U(Qs[ilo * QK_STR + k0 + t]);
                uint32_t a1 = AS_U(Qs[ihi * QK_STR + k0 + t]);
                uint32_t a2 = AS_U(Qs[ilo * QK_STR + k0 + t + 4]);
                uint32_t a3 = AS_U(Qs[ihi * QK_STR + k0 + t + 4]);
#pragma unroll
                for (int nt = 0; nt < 8; nt++) {
                    int n0 = nt * 8;
                    uint32_t b0 = AS_U(tf32r(Ss[(k0 + t) * V_STR + n0 + gq]));
                    uint32_t b1 = AS_U(tf32r(Ss[(k0 + t + 4) * V_STR + n0 + gq]));
                    mma8(acc2[nt], a0, a1, a2, a3, b0, b1);
                }
            }
        }

        // ---- GEMM3: KtV partial state (regs) ----
        float acc3[4][4];
#pragma unroll
        for (int i = 0; i < 4; i++)
#pragma unroll
            for (int j = 0; j < 4; j++) acc3[i][j] = 0.f;
#pragma unroll
        for (int kt = 0; kt < 16; kt++) {
            int k0 = kt * 8;
            uint32_t a0 = AS_U(Ks[(k0 + t) * QK_STR + d0 + gq]);
            uint32_t a1 = AS_U(Ks[(k0 + t) * QK_STR + d0 + gq + 8]);
            uint32_t a2 = AS_U(Ks[(k0 + t + 4) * QK_STR + d0 + gq]);
            uint32_t a3 = AS_U(Ks[(k0 + t + 4) * QK_STR + d0 + gq + 8]);
#pragma unroll
            for (int nt = 0; nt < 4; nt++) {
                int n0 = nb + nt * 8;
                uint32_t b0 = AS_U(Vs[(k0 + t) * V_STR + n0 + gq]);
                uint32_t b1 = AS_U(Vs[(k0 + t + 4) * V_STR + n0 + gq]);
                mma8(acc3[nt], a0, a1, a2, a3, b0, b1);
            }
        }
        float ksum = 0.f;
        if (tid < DD) {
#pragma unroll 8
            for (int j = 0; j < CC; j++) ksum += Ks[j * QK_STR + tid];
        }
        __syncthreads();                                   // S2

        // ---- state update ----
#pragma unroll
        for (int nt = 0; nt < 4; nt++) {
            int n0 = nb + nt * 8 + 2 * t;
            float2* s0 = (float2*)(Ss + (d0 + gq) * V_STR + n0);
            float2* s1 = (float2*)(Ss + (d0 + gq + 8) * V_STR + n0);
            float2 v0 = *s0, v1 = *s1;
            v0.x += acc3[nt][0]; v0.y += acc3[nt][1];
            v1.x += acc3[nt][2]; v1.y += acc3[nt][3];
            *s0 = v0; *s1 = v1;
        }
        if (tid < DD) kc[tid] += ksum;

        // ---- epilogue: direct STG.64 (each quad writes full 32B sectors) ----
        float* orow_lo = out + base + (size_t)ilo * HH * DD;
        float* orow_hi = out + base + (size_t)ihi * HH * DD;
#pragma unroll
        for (int nt = 0; nt < 8; nt++) {
            int n0 = nt * 8 + 2 * t;
            *(float2*)(orow_lo + n0) =
                make_float2(acc2[nt][0] * izlo, acc2[nt][1] * izlo);
            *(float2*)(orow_hi + n0) =
                make_float2(acc2[nt][2] * izhi, acc2[nt][3] * izhi);
        }
    }
}

// ---------------------------------------------------------------------------

extern "C" void kernel_launch(void* const* d_in, const int* in_sizes, int n_in,
                              void* d_out, int out_size) {
    const float* q = (const float*)d_in[0];
    const float* k = (const float*)d_in[1];
    const float* v = (const float*)d_in[2];
    float* out = (float*)d_out;

    cudaFuncSetAttribute(fused_lin_attn,
                         cudaFuncAttributeMaxDynamicSharedMemorySize, SMEM_BYTES);
    fused_lin_attn<<<NP, 256, SMEM_BYTES>>>(q, k, v, out);
}